// round 16
// baseline (speedup 1.0000x reference)
#include <cuda_runtime.h>
#include <cuda_fp16.h>
#include <cuda_bf16.h>
#include <cstdint>

// Problem constants (fixed by dataset; runtime values read from in_sizes).
#define NMAX 50000
#define EMAX 600000

// ---------------- scratch (device globals; no allocation allowed) ----------
// All mutable state is rebuilt every launch; counters/flags are returned to
// zero at the end of each launch -> deterministic across graph replays.
__device__ int   g_cnt[NMAX];
__device__ int   g_rowptr[NMAX + 1];
__device__ int   g_wptr[NMAX];
__device__ int   g_esrc[EMAX];
__device__ float g_dinv[NMAX];
__device__ float g_H[(size_t)NMAX * 128];   // fp32 view (layer 3) / fp16 view (1-2)
__device__ float g_A[(size_t)NMAX * 128];   // activations (fp16 views for 1-2)
__device__ volatile int g_btot[64];   // scan block totals (+1 = published)
__device__ int   g_bdone;             // scan completion counter

// ---------------- helpers --------------------------------------------------
__device__ __forceinline__ uint32_t f2tf32(float f) {
    uint32_t u;
    asm("cvt.rna.tf32.f32 %0, %1;" : "=r"(u) : "f"(f));
    return u;
}

__device__ __forceinline__ void mma_tf32(float c[4],
                                         uint32_t a0, uint32_t a1,
                                         uint32_t a2, uint32_t a3,
                                         uint32_t b0, uint32_t b1) {
    asm volatile(
        "mma.sync.aligned.m16n8k8.row.col.f32.tf32.tf32.f32 "
        "{%0,%1,%2,%3}, {%4,%5,%6,%7}, {%8,%9}, {%0,%1,%2,%3};"
        : "+f"(c[0]), "+f"(c[1]), "+f"(c[2]), "+f"(c[3])
        : "r"(a0), "r"(a1), "r"(a2), "r"(a3), "r"(b0), "r"(b1));
}

__device__ __forceinline__ __half2 u2h2(uint32_t u) {
    return *reinterpret_cast<__half2*>(&u);
}
__device__ __forceinline__ uint32_t h22u(__half2 h) {
    return *reinterpret_cast<uint32_t*>(&h);
}

// ---------------- CSR build (full-grid count + 49-block scan) --------------
__global__ void k_count(const int* __restrict__ dst, int e) {
    int i = blockIdx.x * blockDim.x + threadIdx.x;
    int base = i * 4;
    if (base + 3 < e) {
        int4 d = *(const int4*)(dst + base);
        atomicAdd(&g_cnt[d.x], 1);
        atomicAdd(&g_cnt[d.y], 1);
        atomicAdd(&g_cnt[d.z], 1);
        atomicAdd(&g_cnt[d.w], 1);
    } else {
        for (int k = base; k < e; k++) atomicAdd(&g_cnt[dst[k]], 1);
    }
}

// Single-kernel scan (warp-shuffle + publish/poll; all 49 blocks co-resident).
__global__ __launch_bounds__(1024)
void k_scan_fused(int n, int nb) {
    __shared__ int warpsum[32];
    __shared__ int s_part[64];
    __shared__ int s_off;

    const int bid = blockIdx.x, tid = threadIdx.x;
    const int lane = tid & 31, wid = tid >> 5;
    const int i = bid * 1024 + tid;
    int v = (i < n) ? g_cnt[i] : 0;

    int x = v;
#pragma unroll
    for (int o = 1; o < 32; o <<= 1) {
        int t = __shfl_up_sync(0xffffffffu, x, o);
        if (lane >= o) x += t;
    }
    if (lane == 31) warpsum[wid] = x;
    __syncthreads();
    if (wid == 0) {
        int wx = warpsum[lane];
#pragma unroll
        for (int o = 1; o < 32; o <<= 1) {
            int t = __shfl_up_sync(0xffffffffu, wx, o);
            if (lane >= o) wx += t;
        }
        warpsum[lane] = wx;
    }
    __syncthreads();
    const int basew = (wid == 0) ? 0 : warpsum[wid - 1];
    const int ex  = basew + x - v;
    const int tot = warpsum[31];

    if (tid == 0) atomicExch((int*)&g_btot[bid], tot + 1);

    if (tid < bid) {
        int val;
        do { val = atomicAdd((int*)&g_btot[tid], 0); } while (val == 0);
        s_part[tid] = val - 1;
    }
    __syncthreads();
    if (tid == 0) {
        int off = 0;
        for (int b = 0; b < bid; b++) off += s_part[b];
        s_off = off;
    }
    __syncthreads();
    const int off = s_off;

    if (i < n) {
        int rp = off + ex;
        g_rowptr[i] = rp;
        g_wptr[i]   = rp;
        g_dinv[i]   = rsqrtf((float)v + 1.0f);  // +1 self loop
        g_cnt[i]    = 0;                        // reset for next launch
    }
    if (bid == nb - 1 && tid == 1023) g_rowptr[n] = off + tot;  // == e

    __syncthreads();
    if (tid == 0) {
        int d = atomicAdd(&g_bdone, 1);
        if (d == nb - 1) {
            for (int b = 0; b < nb; b++) g_btot[b] = 0;
            g_bdone = 0;
        }
    }
}

// ---------------- tf32 tensor-core GEMM, double-buffered + pipelined -------
// Out[n,M] = (In[n,K] @ W[K,M]) * dinv[row]
// In fp32 (HIN=false) or fp16 (HIN=true); Out fp16 (HOUT) or fp32.
template <int K, int M>
struct GemmCfg {
    static constexpr int WC = (M >= 64) ? 2 : 1;
    static constexpr int NG = M / (8 * WC);
    static constexpr int WR = 8 / WC;
    static constexpr int BM = WR * 32;
    static constexpr int KC = 32;
    static constexpr int LD = 20;
    static constexpr int NC = K / KC;
    static constexpr int BUFSZ = (BM + M) * LD;              // uint2 per buffer
    static constexpr int SMEM  = 2 * BUFSZ * (int)sizeof(uint2);
};

template <int K, int M, bool HIN, bool HOUT>
__device__ __forceinline__ void gemm_tile(const void* __restrict__ Inv,
                                          const float* __restrict__ W,
                                          void* __restrict__ Outv,
                                          int n, int bid) {
    using C = GemmCfg<K, M>;
    constexpr int NG = C::NG, BM = C::BM, KC = C::KC, LD = C::LD, NC = C::NC;
    constexpr int ASTG = (BM * 4) / 256;
    constexpr int BCNT = M * 4;
    constexpr int BSTG = (BCNT + 255) / 256;

    extern __shared__ uint2 dyn[];

    const int tid  = threadIdx.x;
    const int warp = tid >> 5, lane = tid & 31;
    const int gid  = lane >> 2;
    const int tig  = lane & 3;
    const int row0 = bid * BM;
    const int wr   = (C::WC == 2) ? (warp >> 1) : warp;
    const int wc   = (C::WC == 2) ? (warp & 1) : 0;
    const int rbase = wr * 32;
    const int cbase = wc * NG * 8;

    float4 apre[ASTG][2];
    float  bpre[BSTG][8];

    auto load_chunk = [&](int kk) {
#pragma unroll
        for (int s = 0; s < ASTG; s++) {
            int idx = tid + s * 256;
            int r = idx >> 2, k8 = idx & 3;
            int gr = row0 + r;
            if (gr < n) {
                if constexpr (HIN) {
                    const __half* p = (const __half*)Inv + (size_t)gr * K + kk + k8 * 8;
                    uint4 u = *(const uint4*)p;
                    float2 f0 = __half22float2(u2h2(u.x));
                    float2 f1 = __half22float2(u2h2(u.y));
                    float2 f2 = __half22float2(u2h2(u.z));
                    float2 f3 = __half22float2(u2h2(u.w));
                    apre[s][0] = make_float4(f0.x, f0.y, f1.x, f1.y);
                    apre[s][1] = make_float4(f2.x, f2.y, f3.x, f3.y);
                } else {
                    const float* p = (const float*)Inv + (size_t)gr * K + kk + k8 * 8;
                    apre[s][0] = *(const float4*)p;
                    apre[s][1] = *(const float4*)(p + 4);
                }
            } else {
                apre[s][0] = make_float4(0.f, 0.f, 0.f, 0.f);
                apre[s][1] = apre[s][0];
            }
        }
#pragma unroll
        for (int s = 0; s < BSTG; s++) {
            int idx = tid + s * 256;
            if (idx < BCNT) {
                int c = idx % M, k8 = idx / M;
                const float* p = W + (size_t)(kk + k8 * 8) * M + c;
#pragma unroll
                for (int t = 0; t < 8; t++) bpre[s][t] = p[(size_t)t * M];
            }
        }
    };

    auto store_chunk = [&](int buf) {
        uint2* Ap = dyn + buf * C::BUFSZ;       // [BM][LD]
        uint2* Bp = Ap + BM * LD;               // [M][LD]
#pragma unroll
        for (int s = 0; s < ASTG; s++) {
            int idx = tid + s * 256;
            int r = idx >> 2, k8 = idx & 3;
            uint2* q = &Ap[r * LD + k8 * 4];
            q[0] = make_uint2(f2tf32(apre[s][0].x), f2tf32(apre[s][1].x));
            q[1] = make_uint2(f2tf32(apre[s][0].y), f2tf32(apre[s][1].y));
            q[2] = make_uint2(f2tf32(apre[s][0].z), f2tf32(apre[s][1].z));
            q[3] = make_uint2(f2tf32(apre[s][0].w), f2tf32(apre[s][1].w));
        }
#pragma unroll
        for (int s = 0; s < BSTG; s++) {
            int idx = tid + s * 256;
            if (idx < BCNT) {
                int c = idx % M, k8 = idx / M;
                uint2* q = &Bp[c * LD + k8 * 4];
#pragma unroll
                for (int t = 0; t < 4; t++)
                    q[t] = make_uint2(f2tf32(bpre[s][t]), f2tf32(bpre[s][t + 4]));
            }
        }
    };

    float acc[2][NG][4];
#pragma unroll
    for (int rt = 0; rt < 2; rt++)
#pragma unroll
        for (int g = 0; g < NG; g++)
#pragma unroll
            for (int t = 0; t < 4; t++) acc[rt][g][t] = 0.f;

    load_chunk(0);
    store_chunk(0);
    __syncthreads();

    for (int c = 0; c < NC; c++) {
        if (c + 1 < NC) load_chunk((c + 1) * KC);   // LDG overlaps MMA below

        const uint2* Ap = dyn + (c & 1) * C::BUFSZ;
        const uint2* Bp = Ap + BM * LD;
#pragma unroll
        for (int k8 = 0; k8 < KC / 8; k8++) {
            const int kq = k8 * 4 + tig;
            uint2 a00 = Ap[(rbase + gid     ) * LD + kq];
            uint2 a01 = Ap[(rbase + gid + 8 ) * LD + kq];
            uint2 a10 = Ap[(rbase + 16 + gid    ) * LD + kq];
            uint2 a11 = Ap[(rbase + 16 + gid + 8) * LD + kq];
            uint2 b[NG];
#pragma unroll
            for (int g = 0; g < NG; g++)
                b[g] = Bp[(cbase + g * 8 + gid) * LD + kq];
#pragma unroll
            for (int g = 0; g < NG; g++) {
                mma_tf32(acc[0][g], a00.x, a01.x, a00.y, a01.y, b[g].x, b[g].y);
                mma_tf32(acc[1][g], a10.x, a11.x, a10.y, a11.y, b[g].x, b[g].y);
            }
        }

        if (c + 1 < NC) store_chunk((c + 1) & 1);   // other buffer: no WAR
        __syncthreads();                            // one barrier per chunk
    }

    // ---- epilogue: scale by dinv[row]; fp16 or fp32 stores ----
#pragma unroll
    for (int rt = 0; rt < 2; rt++) {
        const int ra = row0 + rbase + rt * 16 + gid;
        const int rb = ra + 8;
        const float sa = (ra < n) ? g_dinv[ra] : 0.f;
        const float sb = (rb < n) ? g_dinv[rb] : 0.f;
#pragma unroll
        for (int g = 0; g < NG; g++) {
            int col = cbase + g * 8 + tig * 2;
            if constexpr (HOUT) {
                __half* O = (__half*)Outv;
                if (ra < n)
                    *(__half2*)(O + (size_t)ra * M + col) =
                        __floats2half2_rn(acc[rt][g][0] * sa, acc[rt][g][1] * sa);
                if (rb < n)
                    *(__half2*)(O + (size_t)rb * M + col) =
                        __floats2half2_rn(acc[rt][g][2] * sb, acc[rt][g][3] * sb);
            } else {
                float* O = (float*)Outv;
                if (ra < n)
                    *(float2*)(O + (size_t)ra * M + col) =
                        make_float2(acc[rt][g][0] * sa, acc[rt][g][1] * sa);
                if (rb < n)
                    *(float2*)(O + (size_t)rb * M + col) =
                        make_float2(acc[rt][g][2] * sb, acc[rt][g][3] * sb);
            }
        }
    }
}

template <int K, int M, bool HIN, bool HOUT>
__global__ __launch_bounds__(256)
void k_gemm_tc(const void* __restrict__ In, const float* __restrict__ W,
               void* __restrict__ Out, int n) {
    gemm_tile<K, M, HIN, HOUT>(In, W, Out, n, blockIdx.x);
}

// GEMM1 (fp32 in, fp16 out) with CSR-fill fused in trailing blocks.
__global__ __launch_bounds__(256)
void k_gemm1_fill(const float* __restrict__ x, const float* __restrict__ W1,
                  void* __restrict__ H, int n,
                  const int* __restrict__ src, const int* __restrict__ dst,
                  int e, int gemm_blocks) {
    if ((int)blockIdx.x < gemm_blocks) {
        gemm_tile<128, 128, false, true>(x, W1, H, n, blockIdx.x);
    } else {
        int nfb = gridDim.x - gemm_blocks;
        int fb  = blockIdx.x - gemm_blocks;
        for (int i = fb * 256 + threadIdx.x; i < e; i += nfb * 256) {
            int s = src[i];
            int d = dst[i];
            int idx = atomicAdd(&g_wptr[d], 1);
            g_esrc[idx] = s;
        }
    }
}

// ---------------- fp16 aggregation (layers 1 & 2): fp16 in, fp16 out -------
// H fp16 pre-scaled: H'[i] = h[i]*dinv[i].
//   A[d] = relu( dinv[d]*(sum H'[src] + H'[d]) + b )   stored fp16
// 4-edge blocks with a depth-2 HADD2 tree per slot: 3 HADD2 + 1 cvt + 2 FADD
// per 4 gathered half2 values (vs 4 cvt + 8 FADD direct) -> ~37% fewer
// warp instructions per edge while keeping register pressure BELOW the
// direct-8 version (only 4 gathered values live). (256, 8) pins occupancy.
template <int M, bool RELU>
__global__ __launch_bounds__(256, 8)
void agg_half_kernel(const __half* __restrict__ H,
                     const float* __restrict__ bias,
                     __half* __restrict__ Out, int n) {
    constexpr int HU = (M >= 128) ? 2 : 1;   // uint32 (half2) units per lane
    constexpr int CF = 2 * HU;               // fp32 accumulators per lane

    int d    = (blockIdx.x * blockDim.x + threadIdx.x) >> 5;
    int lane = threadIdx.x & 31;
    if (d >= n) return;

    const int c0 = lane * CF;
    const float dd = g_dinv[d];

    float acc[CF];

    auto addrow = [&](const __half* row) {   // scalar path (peel/tail)
        if constexpr (HU == 2) {
            uint2 u = *(const uint2*)(row + c0);
            float2 f0 = __half22float2(u2h2(u.x));
            float2 f1 = __half22float2(u2h2(u.y));
            acc[0] += f0.x; acc[1] += f0.y; acc[2] += f1.x; acc[3] += f1.y;
        } else {
            uint32_t u = *(const uint32_t*)(row + c0);
            float2 f0 = __half22float2(u2h2(u));
            acc[0] += f0.x; acc[1] += f0.y;
        }
    };

    // self loop
    {
        const __half* row = H + (size_t)d * M;
        if constexpr (HU == 2) {
            uint2 u = *(const uint2*)(row + c0);
            float2 f0 = __half22float2(u2h2(u.x));
            float2 f1 = __half22float2(u2h2(u.y));
            acc[0] = f0.x; acc[1] = f0.y; acc[2] = f1.x; acc[3] = f1.y;
        } else {
            uint32_t u = *(const uint32_t*)(row + c0);
            float2 f0 = __half22float2(u2h2(u));
            acc[0] = f0.x; acc[1] = f0.y;
        }
    }

    const int jb = g_rowptr[d], je = g_rowptr[d + 1];
    int j = jb;

    while (j < je && (j & 3)) addrow(H + (size_t)g_esrc[j++] * M);

    // 4-edge blocks: LDG.128 broadcast indices, 4 gathers in flight,
    // depth-2 fp16 pairwise tree, one fp32 add per slot.
    for (; j + 4 <= je; j += 4) {
        int4 sa = *(const int4*)&g_esrc[j];
        int s[4] = {sa.x, sa.y, sa.z, sa.w};
        if constexpr (HU == 2) {
            uint2 u[4];
#pragma unroll
            for (int q = 0; q < 4; q++)
                u[q] = *(const uint2*)(H + (size_t)s[q] * M + c0);
            __half2 px = __hadd2(__hadd2(u2h2(u[0].x), u2h2(u[1].x)),
                                 __hadd2(u2h2(u[2].x), u2h2(u[3].x)));
            __half2 py = __hadd2(__hadd2(u2h2(u[0].y), u2h2(u[1].y)),
                                 __hadd2(u2h2(u[2].y), u2h2(u[3].y)));
            float2 f0 = __half22float2(px);
            float2 f1 = __half22float2(py);
            acc[0] += f0.x; acc[1] += f0.y; acc[2] += f1.x; acc[3] += f1.y;
        } else {
            uint32_t u[4];
#pragma unroll
            for (int q = 0; q < 4; q++)
                u[q] = *(const uint32_t*)(H + (size_t)s[q] * M + c0);
            __half2 p = __hadd2(__hadd2(u2h2(u[0]), u2h2(u[1])),
                                __hadd2(u2h2(u[2]), u2h2(u[3])));
            float2 f0 = __half22float2(p);
            acc[0] += f0.x; acc[1] += f0.y;
        }
    }
    while (j < je) addrow(H + (size_t)g_esrc[j++] * M);

#pragma unroll
    for (int t = 0; t < CF; t++) {
        float r = acc[t] * dd + bias[c0 + t];
        acc[t] = RELU ? fmaxf(r, 0.f) : r;
    }

    __half* od = Out + (size_t)d * M + c0;
    if constexpr (HU == 2) {
        __half2 h0 = __floats2half2_rn(acc[0], acc[1]);
        __half2 h1 = __floats2half2_rn(acc[2], acc[3]);
        *(uint2*)od = make_uint2(h22u(h0), h22u(h1));
    } else {
        *(__half2*)od = __floats2half2_rn(acc[0], acc[1]);
    }
}

// ---------------- fp32 aggregation (layer 3, M=16) -------------------------
template <int M, bool RELU>
__global__ __launch_bounds__(256)
void agg_kernel(const float* __restrict__ H, const float* __restrict__ bias,
                float* __restrict__ Out, int n) {
    constexpr int NPW = 32 / M;

    int gwarp = (blockIdx.x * blockDim.x + threadIdx.x) >> 5;
    int lane  = threadIdx.x & 31;
    int d  = gwarp * NPW + lane / M;
    int c0 = lane % M;
    if (d >= n) return;

    const float dd = g_dinv[d];
    float acc = H[(size_t)d * M + c0];   // self loop

    const int jb = g_rowptr[d], je = g_rowptr[d + 1];
    int j = jb;
    while (j < je && (j & 3)) acc += H[(size_t)g_esrc[j++] * M + c0];
    for (; j + 8 <= je; j += 8) {
        int4 sa = *(const int4*)&g_esrc[j];
        int4 sb = *(const int4*)&g_esrc[j + 4];
        int s[8] = {sa.x, sa.y, sa.z, sa.w, sb.x, sb.y, sb.z, sb.w};
        float v[8];
#pragma unroll
        for (int u = 0; u < 8; u++) v[u] = H[(size_t)s[u] * M + c0];
#pragma unroll
        for (int u = 0; u < 8; u++) acc += v[u];
    }
    for (; j + 4 <= je; j += 4) {
        int4 sa = *(const int4*)&g_esrc[j];
        int s[4] = {sa.x, sa.y, sa.z, sa.w};
        float v[4];
#pragma unroll
        for (int u = 0; u < 4; u++) v[u] = H[(size_t)s[u] * M + c0];
#pragma unroll
        for (int u = 0; u < 4; u++) acc += v[u];
    }
    while (j < je) acc += H[(size_t)g_esrc[j++] * M + c0];

    float r = acc * dd + bias[c0];
    Out[(size_t)d * M + c0] = RELU ? fmaxf(r, 0.f) : r;
}

// ---------------- launcher -------------------------------------------------
extern "C" void kernel_launch(void* const* d_in, const int* in_sizes, int n_in,
                              void* d_out, int out_size) {
    const float* x  = (const float*)d_in[0];
    const int*   ei = (const int*)d_in[1];   // [2, E] int32
    const float* W1 = (const float*)d_in[2];
    const float* b1 = (const float*)d_in[3];
    const float* W2 = (const float*)d_in[4];
    const float* b2 = (const float*)d_in[5];
    const float* W3 = (const float*)d_in[6];
    const float* b3 = (const float*)d_in[7];

    const int n = in_sizes[0] / 128;
    const int e = in_sizes[1] / 2;
    const int* src = ei;
    const int* dst = ei + e;

    void *pH = nullptr, *pA = nullptr;
    cudaGetSymbolAddress(&pH, g_H);
    cudaGetSymbolAddress(&pA, g_A);
    float*  Hf = (float*)pH;        // fp32 view (layer 3)
    __half* Hh = (__half*)pH;       // fp16 view (layers 1-2)
    __half* Ah = (__half*)pA;       // fp16 activations (layers 1-2 outputs)
    float* out = (float*)d_out;

    const int nb  = (n + 1023) / 1024;   // 49 <= 64
    const int gb1 = (n + 127) / 128;     // GEMM1 blocks

    constexpr int SM1 = GemmCfg<128, 128>::SMEM;
    constexpr int SM2 = GemmCfg<128, 64>::SMEM;
    constexpr int SM3 = GemmCfg<64, 16>::SMEM;

    cudaFuncSetAttribute(k_gemm1_fill,
                         cudaFuncAttributeMaxDynamicSharedMemorySize, SM1);
    cudaFuncSetAttribute(k_gemm_tc<128, 64, true, true>,
                         cudaFuncAttributeMaxDynamicSharedMemorySize, SM2);
    cudaFuncSetAttribute(k_gemm_tc<64, 16, true, false>,
                         cudaFuncAttributeMaxDynamicSharedMemorySize, SM3);

    // CSR build: full-grid count, then 49-block scan (dinv/wptr ready)
    k_count<<<(e / 4 + 255) / 256, 256>>>(dst, e);
    k_scan_fused<<<nb, 1024>>>(n, nb);

    // Layer 1: GEMM (fp32 in, fp16 out, prescaled) + fused CSR fill;
    //          fp16 agg -> fp16 A, ReLU
    k_gemm1_fill<<<gb1 + 148, 256, SM1>>>(x, W1, Hh, n, src, dst, e, gb1);
    agg_half_kernel<128, true><<<(n + 7) / 8, 256>>>(Hh, b1, Ah, n);

    // Layer 2: 128 -> 64, fp16 in/out GEMM; fp16 agg -> fp16 A, ReLU
    k_gemm_tc<128, 64, true, true><<<(n + 127) / 128, 256, SM2>>>(Ah, W2, Hh, n);
    agg_half_kernel<64, true><<<(n + 7) / 8, 256>>>(Hh, b2, Ah, n);

    // Layer 3: 64 -> 16, fp16 in / fp32 out; fp32 agg -> output
    k_gemm_tc<64, 16, true, false><<<(n + 255) / 256, 256, SM3>>>(Ah, W3, Hf, n);
    {
        const int NPW = 2;
        int warps  = (n + NPW - 1) / NPW;
        int blocks = (warps * 32 + 255) / 256;
        agg_kernel<16, false><<<blocks, 256>>>(Hf, b3, out, n);
    }
}

// round 17
// speedup vs baseline: 1.0431x; 1.0431x over previous
#include <cuda_runtime.h>
#include <cuda_fp16.h>
#include <cuda_bf16.h>
#include <cstdint>

// Problem constants (fixed by dataset; runtime values read from in_sizes).
#define NMAX 50000
#define EMAX 600000

// ---------------- scratch (device globals; no allocation allowed) ----------
// All mutable state is rebuilt every launch; counters/flags are returned to
// zero at the end of each launch -> deterministic across graph replays.
__device__ int   g_cnt[NMAX];
__device__ int   g_rowptr[NMAX + 1];
__device__ int   g_wptr[NMAX];
__device__ int   g_esrc[EMAX];
__device__ float g_dinv[NMAX];
__device__ float g_H[(size_t)NMAX * 128];   // fp16 views per layer
__device__ float g_A[(size_t)NMAX * 128];   // fp16 activations (layers 1-2)
__device__ volatile int g_btot[64];   // scan block totals (+1 = published)
__device__ int   g_bdone;             // scan completion counter

// ---------------- helpers --------------------------------------------------
__device__ __forceinline__ uint32_t f2tf32(float f) {
    uint32_t u;
    asm("cvt.rna.tf32.f32 %0, %1;" : "=r"(u) : "f"(f));
    return u;
}

__device__ __forceinline__ void mma_tf32(float c[4],
                                         uint32_t a0, uint32_t a1,
                                         uint32_t a2, uint32_t a3,
                                         uint32_t b0, uint32_t b1) {
    asm volatile(
        "mma.sync.aligned.m16n8k8.row.col.f32.tf32.tf32.f32 "
        "{%0,%1,%2,%3}, {%4,%5,%6,%7}, {%8,%9}, {%0,%1,%2,%3};"
        : "+f"(c[0]), "+f"(c[1]), "+f"(c[2]), "+f"(c[3])
        : "r"(a0), "r"(a1), "r"(a2), "r"(a3), "r"(b0), "r"(b1));
}

__device__ __forceinline__ __half2 u2h2(uint32_t u) {
    return *reinterpret_cast<__half2*>(&u);
}
__device__ __forceinline__ uint32_t h22u(__half2 h) {
    return *reinterpret_cast<uint32_t*>(&h);
}

// ---------------- CSR build (full-grid count + 49-block scan) --------------
__global__ void k_count(const int* __restrict__ dst, int e) {
    int i = blockIdx.x * blockDim.x + threadIdx.x;
    int base = i * 4;
    if (base + 3 < e) {
        int4 d = *(const int4*)(dst + base);
        atomicAdd(&g_cnt[d.x], 1);
        atomicAdd(&g_cnt[d.y], 1);
        atomicAdd(&g_cnt[d.z], 1);
        atomicAdd(&g_cnt[d.w], 1);
    } else {
        for (int k = base; k < e; k++) atomicAdd(&g_cnt[dst[k]], 1);
    }
}

// Single-kernel scan (warp-shuffle + publish/poll; all 49 blocks co-resident).
__global__ __launch_bounds__(1024)
void k_scan_fused(int n, int nb) {
    __shared__ int warpsum[32];
    __shared__ int s_part[64];
    __shared__ int s_off;

    const int bid = blockIdx.x, tid = threadIdx.x;
    const int lane = tid & 31, wid = tid >> 5;
    const int i = bid * 1024 + tid;
    int v = (i < n) ? g_cnt[i] : 0;

    int x = v;
#pragma unroll
    for (int o = 1; o < 32; o <<= 1) {
        int t = __shfl_up_sync(0xffffffffu, x, o);
        if (lane >= o) x += t;
    }
    if (lane == 31) warpsum[wid] = x;
    __syncthreads();
    if (wid == 0) {
        int wx = warpsum[lane];
#pragma unroll
        for (int o = 1; o < 32; o <<= 1) {
            int t = __shfl_up_sync(0xffffffffu, wx, o);
            if (lane >= o) wx += t;
        }
        warpsum[lane] = wx;
    }
    __syncthreads();
    const int basew = (wid == 0) ? 0 : warpsum[wid - 1];
    const int ex  = basew + x - v;
    const int tot = warpsum[31];

    if (tid == 0) atomicExch((int*)&g_btot[bid], tot + 1);

    if (tid < bid) {
        int val;
        do { val = atomicAdd((int*)&g_btot[tid], 0); } while (val == 0);
        s_part[tid] = val - 1;
    }
    __syncthreads();
    if (tid == 0) {
        int off = 0;
        for (int b = 0; b < bid; b++) off += s_part[b];
        s_off = off;
    }
    __syncthreads();
    const int off = s_off;

    if (i < n) {
        int rp = off + ex;
        g_rowptr[i] = rp;
        g_wptr[i]   = rp;
        g_dinv[i]   = rsqrtf((float)v + 1.0f);  // +1 self loop
        g_cnt[i]    = 0;                        // reset for next launch
    }
    if (bid == nb - 1 && tid == 1023) g_rowptr[n] = off + tot;  // == e

    __syncthreads();
    if (tid == 0) {
        int d = atomicAdd(&g_bdone, 1);
        if (d == nb - 1) {
            for (int b = 0; b < nb; b++) g_btot[b] = 0;
            g_bdone = 0;
        }
    }
}

// ---------------- tf32 tensor-core GEMM, double-buffered + pipelined -------
// Out[n,M] = (In[n,K] @ W[K,M]) * dinv[row]
// In fp32 (HIN=false) or fp16 (HIN=true); Out fp16 (HOUT) or fp32.
template <int K, int M>
struct GemmCfg {
    static constexpr int WC = (M >= 64) ? 2 : 1;
    static constexpr int NG = M / (8 * WC);
    static constexpr int WR = 8 / WC;
    static constexpr int BM = WR * 32;
    static constexpr int KC = 32;
    static constexpr int LD = 20;
    static constexpr int NC = K / KC;
    static constexpr int BUFSZ = (BM + M) * LD;              // uint2 per buffer
    static constexpr int SMEM  = 2 * BUFSZ * (int)sizeof(uint2);
};

template <int K, int M, bool HIN, bool HOUT>
__device__ __forceinline__ void gemm_tile(const void* __restrict__ Inv,
                                          const float* __restrict__ W,
                                          void* __restrict__ Outv,
                                          int n, int bid) {
    using C = GemmCfg<K, M>;
    constexpr int NG = C::NG, BM = C::BM, KC = C::KC, LD = C::LD, NC = C::NC;
    constexpr int ASTG = (BM * 4) / 256;
    constexpr int BCNT = M * 4;
    constexpr int BSTG = (BCNT + 255) / 256;

    extern __shared__ uint2 dyn[];

    const int tid  = threadIdx.x;
    const int warp = tid >> 5, lane = tid & 31;
    const int gid  = lane >> 2;
    const int tig  = lane & 3;
    const int row0 = bid * BM;
    const int wr   = (C::WC == 2) ? (warp >> 1) : warp;
    const int wc   = (C::WC == 2) ? (warp & 1) : 0;
    const int rbase = wr * 32;
    const int cbase = wc * NG * 8;

    float4 apre[ASTG][2];
    float  bpre[BSTG][8];

    auto load_chunk = [&](int kk) {
#pragma unroll
        for (int s = 0; s < ASTG; s++) {
            int idx = tid + s * 256;
            int r = idx >> 2, k8 = idx & 3;
            int gr = row0 + r;
            if (gr < n) {
                if constexpr (HIN) {
                    const __half* p = (const __half*)Inv + (size_t)gr * K + kk + k8 * 8;
                    uint4 u = *(const uint4*)p;
                    float2 f0 = __half22float2(u2h2(u.x));
                    float2 f1 = __half22float2(u2h2(u.y));
                    float2 f2 = __half22float2(u2h2(u.z));
                    float2 f3 = __half22float2(u2h2(u.w));
                    apre[s][0] = make_float4(f0.x, f0.y, f1.x, f1.y);
                    apre[s][1] = make_float4(f2.x, f2.y, f3.x, f3.y);
                } else {
                    const float* p = (const float*)Inv + (size_t)gr * K + kk + k8 * 8;
                    apre[s][0] = *(const float4*)p;
                    apre[s][1] = *(const float4*)(p + 4);
                }
            } else {
                apre[s][0] = make_float4(0.f, 0.f, 0.f, 0.f);
                apre[s][1] = apre[s][0];
            }
        }
#pragma unroll
        for (int s = 0; s < BSTG; s++) {
            int idx = tid + s * 256;
            if (idx < BCNT) {
                int c = idx % M, k8 = idx / M;
                const float* p = W + (size_t)(kk + k8 * 8) * M + c;
#pragma unroll
                for (int t = 0; t < 8; t++) bpre[s][t] = p[(size_t)t * M];
            }
        }
    };

    auto store_chunk = [&](int buf) {
        uint2* Ap = dyn + buf * C::BUFSZ;       // [BM][LD]
        uint2* Bp = Ap + BM * LD;               // [M][LD]
#pragma unroll
        for (int s = 0; s < ASTG; s++) {
            int idx = tid + s * 256;
            int r = idx >> 2, k8 = idx & 3;
            uint2* q = &Ap[r * LD + k8 * 4];
            q[0] = make_uint2(f2tf32(apre[s][0].x), f2tf32(apre[s][1].x));
            q[1] = make_uint2(f2tf32(apre[s][0].y), f2tf32(apre[s][1].y));
            q[2] = make_uint2(f2tf32(apre[s][0].z), f2tf32(apre[s][1].z));
            q[3] = make_uint2(f2tf32(apre[s][0].w), f2tf32(apre[s][1].w));
        }
#pragma unroll
        for (int s = 0; s < BSTG; s++) {
            int idx = tid + s * 256;
            if (idx < BCNT) {
                int c = idx % M, k8 = idx / M;
                uint2* q = &Bp[c * LD + k8 * 4];
#pragma unroll
                for (int t = 0; t < 4; t++)
                    q[t] = make_uint2(f2tf32(bpre[s][t]), f2tf32(bpre[s][t + 4]));
            }
        }
    };

    float acc[2][NG][4];
#pragma unroll
    for (int rt = 0; rt < 2; rt++)
#pragma unroll
        for (int g = 0; g < NG; g++)
#pragma unroll
            for (int t = 0; t < 4; t++) acc[rt][g][t] = 0.f;

    load_chunk(0);
    store_chunk(0);
    __syncthreads();

    for (int c = 0; c < NC; c++) {
        if (c + 1 < NC) load_chunk((c + 1) * KC);   // LDG overlaps MMA below

        const uint2* Ap = dyn + (c & 1) * C::BUFSZ;
        const uint2* Bp = Ap + BM * LD;
#pragma unroll
        for (int k8 = 0; k8 < KC / 8; k8++) {
            const int kq = k8 * 4 + tig;
            uint2 a00 = Ap[(rbase + gid     ) * LD + kq];
            uint2 a01 = Ap[(rbase + gid + 8 ) * LD + kq];
            uint2 a10 = Ap[(rbase + 16 + gid    ) * LD + kq];
            uint2 a11 = Ap[(rbase + 16 + gid + 8) * LD + kq];
            uint2 b[NG];
#pragma unroll
            for (int g = 0; g < NG; g++)
                b[g] = Bp[(cbase + g * 8 + gid) * LD + kq];
#pragma unroll
            for (int g = 0; g < NG; g++) {
                mma_tf32(acc[0][g], a00.x, a01.x, a00.y, a01.y, b[g].x, b[g].y);
                mma_tf32(acc[1][g], a10.x, a11.x, a10.y, a11.y, b[g].x, b[g].y);
            }
        }

        if (c + 1 < NC) store_chunk((c + 1) & 1);   // other buffer: no WAR
        __syncthreads();                            // one barrier per chunk
    }

    // ---- epilogue: scale by dinv[row]; fp16 or fp32 stores ----
#pragma unroll
    for (int rt = 0; rt < 2; rt++) {
        const int ra = row0 + rbase + rt * 16 + gid;
        const int rb = ra + 8;
        const float sa = (ra < n) ? g_dinv[ra] : 0.f;
        const float sb = (rb < n) ? g_dinv[rb] : 0.f;
#pragma unroll
        for (int g = 0; g < NG; g++) {
            int col = cbase + g * 8 + tig * 2;
            if constexpr (HOUT) {
                __half* O = (__half*)Outv;
                if (ra < n)
                    *(__half2*)(O + (size_t)ra * M + col) =
                        __floats2half2_rn(acc[rt][g][0] * sa, acc[rt][g][1] * sa);
                if (rb < n)
                    *(__half2*)(O + (size_t)rb * M + col) =
                        __floats2half2_rn(acc[rt][g][2] * sb, acc[rt][g][3] * sb);
            } else {
                float* O = (float*)Outv;
                if (ra < n)
                    *(float2*)(O + (size_t)ra * M + col) =
                        make_float2(acc[rt][g][0] * sa, acc[rt][g][1] * sa);
                if (rb < n)
                    *(float2*)(O + (size_t)rb * M + col) =
                        make_float2(acc[rt][g][2] * sb, acc[rt][g][3] * sb);
            }
        }
    }
}

template <int K, int M, bool HIN, bool HOUT>
__global__ __launch_bounds__(256)
void k_gemm_tc(const void* __restrict__ In, const float* __restrict__ W,
               void* __restrict__ Out, int n) {
    gemm_tile<K, M, HIN, HOUT>(In, W, Out, n, blockIdx.x);
}

// GEMM1 (fp32 in, fp16 out) with CSR-fill fused in trailing blocks.
__global__ __launch_bounds__(256)
void k_gemm1_fill(const float* __restrict__ x, const float* __restrict__ W1,
                  void* __restrict__ H, int n,
                  const int* __restrict__ src, const int* __restrict__ dst,
                  int e, int gemm_blocks) {
    if ((int)blockIdx.x < gemm_blocks) {
        gemm_tile<128, 128, false, true>(x, W1, H, n, blockIdx.x);
    } else {
        int nfb = gridDim.x - gemm_blocks;
        int fb  = blockIdx.x - gemm_blocks;
        for (int i = fb * 256 + threadIdx.x; i < e; i += nfb * 256) {
            int s = src[i];
            int d = dst[i];
            int idx = atomicAdd(&g_wptr[d], 1);
            g_esrc[idx] = s;
        }
    }
}

// ---------------- fp16 aggregation (layers 1 & 2): fp16 in, fp16 out -------
// H fp16 pre-scaled: H'[i] = h[i]*dinv[i].
//   A[d] = relu( dinv[d]*(sum H'[src] + H'[d]) + b )   stored fp16
// R14-proven direct convert + fp32 accumulate (32 regs, ~80% occupancy).
template <int M, bool RELU>
__global__ __launch_bounds__(256, 8)
void agg_half_kernel(const __half* __restrict__ H,
                     const float* __restrict__ bias,
                     __half* __restrict__ Out, int n) {
    constexpr int HU = (M >= 128) ? 2 : 1;   // uint32 (half2) units per lane
    constexpr int CF = 2 * HU;               // fp32 accumulators per lane

    int d    = (blockIdx.x * blockDim.x + threadIdx.x) >> 5;
    int lane = threadIdx.x & 31;
    if (d >= n) return;

    const int c0 = lane * CF;
    const float dd = g_dinv[d];

    float acc[CF];

    auto addrow = [&](const __half* row) {   // scalar path (peel/tail)
        if constexpr (HU == 2) {
            uint2 u = *(const uint2*)(row + c0);
            float2 f0 = __half22float2(u2h2(u.x));
            float2 f1 = __half22float2(u2h2(u.y));
            acc[0] += f0.x; acc[1] += f0.y; acc[2] += f1.x; acc[3] += f1.y;
        } else {
            uint32_t u = *(const uint32_t*)(row + c0);
            float2 f0 = __half22float2(u2h2(u));
            acc[0] += f0.x; acc[1] += f0.y;
        }
    };

    // self loop
    {
        const __half* row = H + (size_t)d * M;
        if constexpr (HU == 2) {
            uint2 u = *(const uint2*)(row + c0);
            float2 f0 = __half22float2(u2h2(u.x));
            float2 f1 = __half22float2(u2h2(u.y));
            acc[0] = f0.x; acc[1] = f0.y; acc[2] = f1.x; acc[3] = f1.y;
        } else {
            uint32_t u = *(const uint32_t*)(row + c0);
            float2 f0 = __half22float2(u2h2(u));
            acc[0] = f0.x; acc[1] = f0.y;
        }
    }

    const int jb = g_rowptr[d], je = g_rowptr[d + 1];
    int j = jb;

    while (j < je && (j & 3)) addrow(H + (size_t)g_esrc[j++] * M);

    // 8-edge blocks: 2 x LDG.128 broadcast indices, 8 gathers in flight
    for (; j + 8 <= je; j += 8) {
        int4 sa = *(const int4*)&g_esrc[j];
        int4 sb = *(const int4*)&g_esrc[j + 4];
        int s[8] = {sa.x, sa.y, sa.z, sa.w, sb.x, sb.y, sb.z, sb.w};
        if constexpr (HU == 2) {
            uint2 u[8];
#pragma unroll
            for (int q = 0; q < 8; q++)
                u[q] = *(const uint2*)(H + (size_t)s[q] * M + c0);
#pragma unroll
            for (int q = 0; q < 8; q++) {
                float2 f0 = __half22float2(u2h2(u[q].x));
                float2 f1 = __half22float2(u2h2(u[q].y));
                acc[0] += f0.x; acc[1] += f0.y; acc[2] += f1.x; acc[3] += f1.y;
            }
        } else {
            uint32_t u[8];
#pragma unroll
            for (int q = 0; q < 8; q++)
                u[q] = *(const uint32_t*)(H + (size_t)s[q] * M + c0);
#pragma unroll
            for (int q = 0; q < 8; q++) {
                float2 f0 = __half22float2(u2h2(u[q]));
                acc[0] += f0.x; acc[1] += f0.y;
            }
        }
    }
    for (; j + 4 <= je; j += 4) {
        int4 sa = *(const int4*)&g_esrc[j];
        int s[4] = {sa.x, sa.y, sa.z, sa.w};
#pragma unroll
        for (int q = 0; q < 4; q++) addrow(H + (size_t)s[q] * M);
    }
    while (j < je) addrow(H + (size_t)g_esrc[j++] * M);

#pragma unroll
    for (int t = 0; t < CF; t++) {
        float r = acc[t] * dd + bias[c0 + t];
        acc[t] = RELU ? fmaxf(r, 0.f) : r;
    }

    __half* od = Out + (size_t)d * M + c0;
    if constexpr (HU == 2) {
        __half2 h0 = __floats2half2_rn(acc[0], acc[1]);
        __half2 h1 = __floats2half2_rn(acc[2], acc[3]);
        *(uint2*)od = make_uint2(h22u(h0), h22u(h1));
    } else {
        *(__half2*)od = __floats2half2_rn(acc[0], acc[1]);
    }
}

// ---------------- layer-3 aggregation: fp16 H3 in, fp32 out ----------------
// M=16 halves per row = 32 B. 4 nodes/warp, 8 lanes/node, lane loads uint
// (2 halves) at c0 = (lane%8)*2. Accumulate fp32, write 2 floats.
__global__ __launch_bounds__(256, 8)
void agg3_kernel(const __half* __restrict__ H, const float* __restrict__ bias,
                 float* __restrict__ Out, int n) {
    constexpr int M = 16;

    int gwarp = (blockIdx.x * blockDim.x + threadIdx.x) >> 5;
    int lane  = threadIdx.x & 31;
    int d  = gwarp * 4 + (lane >> 3);
    int c0 = (lane & 7) * 2;
    if (d >= n) return;

    const float dd = g_dinv[d];

    float a0, a1;
    {
        uint32_t u = *(const uint32_t*)(H + (size_t)d * M + c0);  // self loop
        float2 f = __half22float2(u2h2(u));
        a0 = f.x; a1 = f.y;
    }

    const int jb = g_rowptr[d], je = g_rowptr[d + 1];
    int j = jb;
    while (j < je && (j & 3)) {
        uint32_t u = *(const uint32_t*)(H + (size_t)g_esrc[j++] * M + c0);
        float2 f = __half22float2(u2h2(u));
        a0 += f.x; a1 += f.y;
    }
    for (; j + 8 <= je; j += 8) {
        int4 sa = *(const int4*)&g_esrc[j];
        int4 sb = *(const int4*)&g_esrc[j + 4];
        int s[8] = {sa.x, sa.y, sa.z, sa.w, sb.x, sb.y, sb.z, sb.w};
        uint32_t u[8];
#pragma unroll
        for (int q = 0; q < 8; q++)
            u[q] = *(const uint32_t*)(H + (size_t)s[q] * M + c0);
#pragma unroll
        for (int q = 0; q < 8; q++) {
            float2 f = __half22float2(u2h2(u[q]));
            a0 += f.x; a1 += f.y;
        }
    }
    for (; j + 4 <= je; j += 4) {
        int4 sa = *(const int4*)&g_esrc[j];
        int s[4] = {sa.x, sa.y, sa.z, sa.w};
        uint32_t u[4];
#pragma unroll
        for (int q = 0; q < 4; q++)
            u[q] = *(const uint32_t*)(H + (size_t)s[q] * M + c0);
#pragma unroll
        for (int q = 0; q < 4; q++) {
            float2 f = __half22float2(u2h2(u[q]));
            a0 += f.x; a1 += f.y;
        }
    }
    while (j < je) {
        uint32_t u = *(const uint32_t*)(H + (size_t)g_esrc[j++] * M + c0);
        float2 f = __half22float2(u2h2(u));
        a0 += f.x; a1 += f.y;
    }

    float* od = Out + (size_t)d * M + c0;
    *(float2*)od = make_float2(a0 * dd + bias[c0], a1 * dd + bias[c0 + 1]);
}

// ---------------- launcher -------------------------------------------------
extern "C" void kernel_launch(void* const* d_in, const int* in_sizes, int n_in,
                              void* d_out, int out_size) {
    const float* x  = (const float*)d_in[0];
    const int*   ei = (const int*)d_in[1];   // [2, E] int32
    const float* W1 = (const float*)d_in[2];
    const float* b1 = (const float*)d_in[3];
    const float* W2 = (const float*)d_in[4];
    const float* b2 = (const float*)d_in[5];
    const float* W3 = (const float*)d_in[6];
    const float* b3 = (const float*)d_in[7];

    const int n = in_sizes[0] / 128;
    const int e = in_sizes[1] / 2;
    const int* src = ei;
    const int* dst = ei + e;

    void *pH = nullptr, *pA = nullptr;
    cudaGetSymbolAddress(&pH, g_H);
    cudaGetSymbolAddress(&pA, g_A);
    __half* Hh = (__half*)pH;       // fp16 view (all layers)
    __half* Ah = (__half*)pA;       // fp16 activations (layers 1-2 outputs)
    float* out = (float*)d_out;

    const int nb  = (n + 1023) / 1024;   // 49 <= 64
    const int gb1 = (n + 127) / 128;     // GEMM1 blocks

    constexpr int SM1 = GemmCfg<128, 128>::SMEM;
    constexpr int SM2 = GemmCfg<128, 64>::SMEM;
    constexpr int SM3 = GemmCfg<64, 16>::SMEM;

    cudaFuncSetAttribute(k_gemm1_fill,
                         cudaFuncAttributeMaxDynamicSharedMemorySize, SM1);
    cudaFuncSetAttribute(k_gemm_tc<128, 64, true, true>,
                         cudaFuncAttributeMaxDynamicSharedMemorySize, SM2);
    cudaFuncSetAttribute(k_gemm_tc<64, 16, true, true>,
                         cudaFuncAttributeMaxDynamicSharedMemorySize, SM3);

    // CSR build: full-grid count, then 49-block scan (dinv/wptr ready)
    k_count<<<(e / 4 + 255) / 256, 256>>>(dst, e);
    k_scan_fused<<<nb, 1024>>>(n, nb);

    // Layer 1: GEMM (fp32 in, fp16 out, prescaled) + fused CSR fill;
    //          fp16 agg -> fp16 A, ReLU
    k_gemm1_fill<<<gb1 + 148, 256, SM1>>>(x, W1, Hh, n, src, dst, e, gb1);
    agg_half_kernel<128, true><<<(n + 7) / 8, 256>>>(Hh, b1, Ah, n);

    // Layer 2: 128 -> 64, fp16 in/out GEMM; fp16 agg -> fp16 A, ReLU
    k_gemm_tc<128, 64, true, true><<<(n + 127) / 128, 256, SM2>>>(Ah, W2, Hh, n);
    agg_half_kernel<64, true><<<(n + 7) / 8, 256>>>(Hh, b2, Ah, n);

    // Layer 3: 64 -> 16, fp16 in / fp16 out; fp16 agg -> fp32 output
    k_gemm_tc<64, 16, true, true><<<(n + 255) / 256, 256, SM3>>>(Ah, W3, Hh, n);
    {
        int warps  = (n + 3) / 4;
        int blocks = (warps * 32 + 255) / 256;
        agg3_kernel<<<blocks, 256>>>(Hh, b3, out, n);
    }
}